// round 1
// baseline (speedup 1.0000x reference)
#include <cuda_runtime.h>
#include <cuda_bf16.h>

// Problem constants
#define BATCH   64
#define CHAN    256
#define HWSZ    1024          // 32*32
#define NROWS   65536         // BATCH*HWSZ
#define KCODES  1024
#define TILE_R  128           // rows per CTA in main kernel
#define TILE_K  128           // codes per k-chunk
#define CI      16            // inner-dim chunk
#define NTILES  512           // NROWS / TILE_R
#define NPART   8192          // 512 tiles * 16 channel-groups

// Scratch (device globals: no allocation allowed)
__device__ float g_esq[KCODES];
__device__ float g_zsq[NROWS];
__device__ int   g_idx[NROWS];
__device__ float g_part[NPART];

// ---------------------------------------------------------------------------
// e_sq[k] = sum_c emb[k,c]^2, sequential-c fp32 FMA chain (mimic reference).
// ---------------------------------------------------------------------------
__global__ void k_esq(const float* __restrict__ emb) {
    int k = blockIdx.x * blockDim.x + threadIdx.x;
    if (k < KCODES) {
        const float* row = emb + (size_t)k * CHAN;
        float acc = 0.0f;
        #pragma unroll 8
        for (int c = 0; c < CHAN; ++c) acc = fmaf(row[c], row[c], acc);
        g_esq[k] = acc;
    }
}

// ---------------------------------------------------------------------------
// z_sq[n] = sum_c z[n,c]^2, sequential-c fp32 FMA chain.
// grid = 512 tiles, 128 threads; thread r owns row (tile*128 + r).
// Loads are coalesced across r for each c.
// ---------------------------------------------------------------------------
__global__ void k_zsq(const float* __restrict__ z) {
    int t   = blockIdx.x;
    int b   = t >> 3;
    int hw0 = (t & 7) << 7;
    int r   = threadIdx.x;                  // 0..127
    const float* base = z + (size_t)b * CHAN * HWSZ + hw0 + r;
    float acc = 0.0f;
    #pragma unroll 8
    for (int c = 0; c < CHAN; ++c) {
        float v = base[(size_t)c * HWSZ];
        acc = fmaf(v, v, acc);
    }
    g_zsq[t * TILE_R + r] = acc;
}

// ---------------------------------------------------------------------------
// Main: per-row argmin over K codes of dist = (z_sq + e_sq) - 2*(z.e)
// z.e accumulated as a single sequential fp32 FMA chain over c = 0..255
// (matches reference rounding domain; ties broken toward lowest k, matching
// jnp.argmin first-occurrence semantics).
// CTA: 256 threads as 16x16; each thread owns an 8x8 (row x code) micro-tile.
// ---------------------------------------------------------------------------
__global__ void __launch_bounds__(256, 2)
k_main(const float* __restrict__ z, const float* __restrict__ emb) {
    __shared__ float Zs[CI][TILE_R + 4];   // [ci][row]
    __shared__ float Es[CI][TILE_K + 4];   // [ci][code]
    __shared__ float cd[TILE_R][17];
    __shared__ int   ck[TILE_R][17];

    int t   = blockIdx.x;
    int b   = t >> 3;
    int hw0 = (t & 7) << 7;
    int tid = threadIdx.x;
    int tx  = tid & 15;
    int ty  = tid >> 4;

    float bestd[8];
    int   bestk[8];
    #pragma unroll
    for (int i = 0; i < 8; ++i) { bestd[i] = 3.4028235e38f; bestk[i] = 0; }

    float zsqr[8];
    #pragma unroll
    for (int i = 0; i < 8; ++i) zsqr[i] = g_zsq[t * TILE_R + ty * 8 + i];

    const float* zbase = z + (size_t)b * CHAN * HWSZ + hw0;

    for (int kc = 0; kc < KCODES; kc += TILE_K) {
        float acc[8][8];
        #pragma unroll
        for (int i = 0; i < 8; ++i)
            #pragma unroll
            for (int j = 0; j < 8; ++j) acc[i][j] = 0.0f;

        for (int cc = 0; cc < CHAN; cc += CI) {
            // Load Z chunk [CI][128]: coalesced along rows.
            {
                int rZ  = tid & 127;
                int ciZ = tid >> 7;            // 0/1
                #pragma unroll
                for (int p = 0; p < 8; ++p) {
                    int ci = p * 2 + ciZ;
                    Zs[ci][rZ] = zbase[(size_t)(cc + ci) * HWSZ + rZ];
                }
            }
            // Load E chunk transposed [CI][128 codes].
            {
                int ciE = tid & 15;
                int kkE = tid >> 4;            // 0..15
                #pragma unroll
                for (int p = 0; p < 8; ++p) {
                    int kk = p * 16 + kkE;
                    Es[ciE][kk] = emb[(size_t)(kc + kk) * CHAN + cc + ciE];
                }
            }
            __syncthreads();

            #pragma unroll
            for (int ci = 0; ci < CI; ++ci) {
                float zr[8], er[8];
                #pragma unroll
                for (int i = 0; i < 8; ++i) zr[i] = Zs[ci][ty * 8 + i];
                #pragma unroll
                for (int j = 0; j < 8; ++j) er[j] = Es[ci][tx * 8 + j];
                #pragma unroll
                for (int i = 0; i < 8; ++i)
                    #pragma unroll
                    for (int j = 0; j < 8; ++j)
                        acc[i][j] = fmaf(zr[i], er[j], acc[i][j]);
            }
            __syncthreads();
        }

        // Fold this k-chunk into the running argmin. Strict '<' keeps the
        // earliest k on exact fp32 ties (j and kc ascend per thread).
        #pragma unroll
        for (int j = 0; j < 8; ++j) {
            int k = kc + tx * 8 + j;
            float es = g_esq[k];
            #pragma unroll
            for (int i = 0; i < 8; ++i) {
                float d = (zsqr[i] + es) - 2.0f * acc[i][j];
                if (d < bestd[i]) { bestd[i] = d; bestk[i] = k; }
            }
        }
    }

    // Cross-thread reduction: lexicographic (d, k) min = first occurrence of
    // the fp32 minimum (jnp.argmin semantics).
    #pragma unroll
    for (int i = 0; i < 8; ++i) {
        cd[ty * 8 + i][tx] = bestd[i];
        ck[ty * 8 + i][tx] = bestk[i];
    }
    __syncthreads();
    if (tid < TILE_R) {
        float bd = cd[tid][0];
        int   bk = ck[tid][0];
        #pragma unroll
        for (int x = 1; x < 16; ++x) {
            float d  = cd[tid][x];
            int   k2 = ck[tid][x];
            if (d < bd || (d == bd && k2 < bk)) { bd = d; bk = k2; }
        }
        g_idx[t * TILE_R + tid] = bk;
    }
}

// ---------------------------------------------------------------------------
// Output + loss partials: out[b,c,hw] = emb[idx[n], c]; accumulate (q-z)^2.
// grid = (512 tiles, 16 channel-groups), 256 threads, deterministic reduce.
// ---------------------------------------------------------------------------
__global__ void k_out(const float* __restrict__ z, const float* __restrict__ emb,
                      float* __restrict__ out) {
    __shared__ int   sidx[TILE_R];
    __shared__ float red[256];

    int t   = blockIdx.x;      // tile over rows
    int cy  = blockIdx.y;      // channel group (16 channels each)
    int b   = t >> 3;
    int hw0 = (t & 7) << 7;
    int tid = threadIdx.x;

    if (tid < TILE_R) sidx[tid] = g_idx[t * TILE_R + tid];
    __syncthreads();

    int r  = tid & 127;
    int ch = tid >> 7;         // 0/1
    float accum = 0.0f;
    #pragma unroll
    for (int p = 0; p < 8; ++p) {
        int c = cy * 16 + p * 2 + ch;
        size_t off = ((size_t)b * CHAN + c) * HWSZ + hw0 + r;
        float q  = emb[(size_t)sidx[r] * CHAN + c];
        float zv = z[off];
        out[off] = q;
        float df = q - zv;
        accum = fmaf(df, df, accum);
    }
    red[tid] = accum;
    __syncthreads();
    #pragma unroll
    for (int s = 128; s > 0; s >>= 1) {
        if (tid < s) red[tid] += red[tid + s];
        __syncthreads();
    }
    if (tid == 0) g_part[cy * NTILES + t] = red[0];
}

// loss = (1 + BETA) * mean((z_q - z)^2); fixed-order reduction (deterministic)
__global__ void k_final(float* __restrict__ out) {
    __shared__ float red[256];
    int tid = threadIdx.x;
    float a = 0.0f;
    for (int i = tid; i < NPART; i += 256) a += g_part[i];
    red[tid] = a;
    __syncthreads();
    #pragma unroll
    for (int s = 128; s > 0; s >>= 1) {
        if (tid < s) red[tid] += red[tid + s];
        __syncthreads();
    }
    if (tid == 0) out[16777216] = 1.25f * (red[0] / 16777216.0f);
}

// ---------------------------------------------------------------------------
extern "C" void kernel_launch(void* const* d_in, const int* in_sizes, int n_in,
                              void* d_out, int out_size) {
    const float* z   = (const float*)d_in[0];   // [64,256,32,32]
    const float* emb = (const float*)d_in[1];   // [1024,256]
    float* out = (float*)d_out;                 // 16777216 z_q + 1 loss

    k_esq<<<8, 128>>>(emb);
    k_zsq<<<NTILES, 128>>>(z);
    k_main<<<NTILES, 256>>>(z, emb);
    dim3 g(NTILES, 16);
    k_out<<<g, 256>>>(z, emb, out);
    k_final<<<1, 256>>>(out);
}